// round 10
// baseline (speedup 1.0000x reference)
#include <cuda_runtime.h>
#include <cuda_bf16.h>
#include <cstdint>

// Problem constants
#define Bb 2
#define Nn 1024
#define Ee 8192
#define Dd 64
#define NT8 8            // 8 tiles of 128 along N
#define PAIRS8 36        // upper-triangular tile pairs
#define KC 32            // K elements per stage
#define KSPLIT 4
#define KQ (Ee / KSPLIT)           // 2048
#define NCHUNK (KQ / KC)           // 64

// ---------------------------------------------------------------------------
// Device scratch
// ---------------------------------------------------------------------------
__device__ float g_scale[Bb * Ee];
__device__ float g_hw[Bb * Nn * Dd];
__device__ float g_part[(size_t)Bb * PAIRS8 * KSPLIT * 128 * 128];
__device__ float g_outp8[NT8][Bb * Nn * Dd];

// ---------------------------------------------------------------------------
// Portable PTX helpers
// ---------------------------------------------------------------------------
__device__ __forceinline__ uint32_t smem_u32(const void* p) {
    uint32_t a;
    asm("{ .reg .u64 t; cvta.to.shared.u64 t, %1; cvt.u32.u64 %0, t; }" : "=r"(a) : "l"(p));
    return a;
}
#define CP16(dst, src) \
    asm volatile("cp.async.cg.shared.global [%0], [%1], 16;" :: "r"(dst), "l"(src))
#define CP_COMMIT() asm volatile("cp.async.commit_group;")
#define CP_WAIT0()  asm volatile("cp.async.wait_group 0;")
#define CP_WAIT1()  asm volatile("cp.async.wait_group 1;")

__device__ __forceinline__ uint32_t f2tf32(float x) {
    uint32_t r;
    asm("cvt.rna.tf32.f32 %0, %1;" : "=r"(r) : "f"(x));
    return r;
}
__device__ __forceinline__ void mma_tf32(float* c, const uint32_t* a, const uint32_t* b) {
    asm volatile(
        "mma.sync.aligned.m16n8k8.row.col.f32.tf32.tf32.f32 "
        "{%0,%1,%2,%3}, {%4,%5,%6,%7}, {%8,%9}, {%0,%1,%2,%3};"
        : "+f"(c[0]), "+f"(c[1]), "+f"(c[2]), "+f"(c[3])
        : "r"(a[0]), "r"(a[1]), "r"(a[2]), "r"(a[3]), "r"(b[0]), "r"(b[1]));
}

// ---------------------------------------------------------------------------
// scale[b,e] = dot(H_e[b,e,:], p)
// ---------------------------------------------------------------------------
__global__ void scale_kernel(const float* __restrict__ H_e,
                             const float* __restrict__ p) {
    __shared__ float ps[64];
    if (threadIdx.x < 64) ps[threadIdx.x] = p[threadIdx.x];
    __syncthreads();
    int r = blockIdx.x * blockDim.x + threadIdx.x;
    if (r < Bb * Ee) {
        const float4* he = reinterpret_cast<const float4*>(H_e + (size_t)r * 64);
        float s = 0.f;
#pragma unroll
        for (int i = 0; i < 16; i++) {
            float4 v = he[i];
            s += v.x * ps[i * 4 + 0] + v.y * ps[i * 4 + 1] +
                 v.z * ps[i * 4 + 2] + v.w * ps[i * 4 + 3];
        }
        g_scale[r] = s;
    }
}

// ---------------------------------------------------------------------------
// HW[r,d] = dot(H_v[r,:], W[:,d])
// ---------------------------------------------------------------------------
__global__ void hw_kernel(const float* __restrict__ H_v,
                          const float* __restrict__ W) {
    __shared__ float ws[64 * 64];
    __shared__ float hv[4][64];
    int tx = threadIdx.x, ty = threadIdx.y;
    int tid = ty * 64 + tx;
    for (int i = tid; i < 64 * 64; i += 256) ws[i] = W[i];
    int row0 = blockIdx.x * 4;
    hv[ty][tx] = H_v[(size_t)(row0 + ty) * 64 + tx];
    __syncthreads();
    float acc = 0.f;
#pragma unroll
    for (int k = 0; k < 64; k++) acc += hv[ty][k] * ws[k * 64 + tx];
    g_hw[(size_t)(row0 + ty) * 64 + tx] = acc;
}

// ---------------------------------------------------------------------------
// mult partial: 128x128 tile, quarter-K per CTA, single-term tf32 m16n8k8.
// Loads RAW f32 T via cp.async for both tiles, then an in-smem fixup pass:
//   A[row][k] = rna_tf32(t * scale[k]),  B[row][k] = rna_tf32(t)
// (same rounding path the old prep kernel used -> identical numerics,
//  but 192 MB of prep traffic and one kernel launch are gone).
// Fixup mapping: thread handles k = tid&31 for rows (tid>>5)+8j ->
// bank = (36*row + k) % 32 = (4row + lane) % 32, conflict-free.
// grid = Bb*PAIRS8*KSPLIT = 288 (~2 CTAs/SM), 256 threads, warp grid 2x4.
// ---------------------------------------------------------------------------
#define STRIDE_W 36
#define STAGE_WORDS (128 * STRIDE_W)           // per array: 4608 words
#define OFF_B_BYTES (STAGE_WORDS * 4)          // 18432
#define STAGE_BYTES (2 * STAGE_WORDS * 4)      // 36864
#define MULT_SMEM (3 * STAGE_BYTES)            // 110592

__global__ void __launch_bounds__(256, 2)
mult_partial(const float* __restrict__ T) {
    extern __shared__ __align__(16) char smraw[];
    uint32_t stg = smem_u32(smraw);
    uint32_t* smw = reinterpret_cast<uint32_t*>(smraw);

    int tid = threadIdx.x;
    int wid = tid >> 5;
    int lid = tid & 31;
    int wm = wid & 1;          // m-half (64 rows)
    int wn = wid >> 1;         // n-quarter (32 cols)

    int p2 = blockIdx.x;
    int pair = p2 >> 2;
    int ksp = p2 & 3;
    int b = pair / PAIRS8;
    int t = pair % PAIRS8;
    int ti = 0, rem = t;
    while (rem >= NT8 - ti) { rem -= NT8 - ti; ti++; }
    int tj = ti + rem;

    size_t rowA = (size_t)(b * Nn + ti * 128);
    size_t rowB = (size_t)(b * Nn + tj * 128);
    int kbase = ksp * KQ;
    const float* scp = g_scale + b * Ee + kbase;

    auto load_stage = [&](int sidx, int k0) {
        uint32_t sb = stg + sidx * STAGE_BYTES;
#pragma unroll
        for (int i = 0; i < 4; i++) {
            int chunk = tid + i * 256;           // 0..1023
            int row = chunk >> 3, cc = chunk & 7;
            uint32_t d = (uint32_t)(row * (STRIDE_W * 4) + cc * 16);
            CP16(sb + d, T + (rowA + row) * (size_t)Ee + k0 + cc * 4);
            CP16(sb + OFF_B_BYTES + d, T + (rowB + row) * (size_t)Ee + k0 + cc * 4);
        }
        CP_COMMIT();
    };

    float acc[4][4][4];
#pragma unroll
    for (int i = 0; i < 4; i++)
#pragma unroll
        for (int j = 0; j < 4; j++)
#pragma unroll
            for (int q = 0; q < 4; q++) acc[i][j][q] = 0.f;

    load_stage(0, kbase);
    load_stage(1, kbase + KC);

    int lrow = lid >> 2;       // 0..7
    int lcol = lid & 3;        // 0..3
    int fx_r0 = tid >> 5;      // fixup: base row 0..7
    int fx_k = tid & 31;       // fixup: k column (== lane)

    for (int s = 0; s < NCHUNK; s++) {
        if (s < NCHUNK - 1) CP_WAIT1(); else CP_WAIT0();
        __syncthreads();
        uint32_t* As = smw + (s % 3) * (STAGE_BYTES / 4);
        uint32_t* Bs = As + STAGE_WORDS;

        // ---- in-smem tf32 fixup (conflict-free scalar) ----
        {
            float sv = scp[s * KC + fx_k];
#pragma unroll
            for (int j = 0; j < 16; j++) {
                int a = (fx_r0 + j * 8) * STRIDE_W + fx_k;
                As[a] = f2tf32(__uint_as_float(As[a]) * sv);
                Bs[a] = f2tf32(__uint_as_float(Bs[a]));
            }
        }
        __syncthreads();

#pragma unroll
        for (int ks = 0; ks < 4; ks++) {
            int kc = ks * 8 + lcol;
            uint32_t af[4][4], bf[4][2];
#pragma unroll
            for (int mt = 0; mt < 4; mt++) {
                int rb = (wm * 64 + mt * 16 + lrow) * STRIDE_W;
                af[mt][0] = As[rb + kc];
                af[mt][1] = As[rb + 8 * STRIDE_W + kc];
                af[mt][2] = As[rb + kc + 4];
                af[mt][3] = As[rb + 8 * STRIDE_W + kc + 4];
            }
#pragma unroll
            for (int nt = 0; nt < 4; nt++) {
                int nb = (wn * 32 + nt * 8 + lrow) * STRIDE_W;
                bf[nt][0] = Bs[nb + kc];
                bf[nt][1] = Bs[nb + kc + 4];
            }
#pragma unroll
            for (int mt = 0; mt < 4; mt++)
#pragma unroll
                for (int nt = 0; nt < 4; nt++)
                    mma_tf32(acc[mt][nt], af[mt], bf[nt]);
        }
        if (s + 2 < NCHUNK) load_stage((s + 2) % 3, kbase + (s + 2) * KC);
    }

    // write partial tile
    float* pt = g_part + (size_t)p2 * 128 * 128;
#pragma unroll
    for (int mt = 0; mt < 4; mt++)
#pragma unroll
        for (int nt = 0; nt < 4; nt++) {
            int r = wm * 64 + mt * 16 + (lid >> 2);
            int c = wn * 32 + nt * 8 + (lid & 3) * 2;
            *reinterpret_cast<float2*>(pt + (size_t)r * 128 + c) =
                make_float2(acc[mt][nt][0], acc[mt][nt][1]);
            *reinterpret_cast<float2*>(pt + (size_t)(r + 8) * 128 + c) =
                make_float2(acc[mt][nt][2], acc[mt][nt][3]);
        }
}

// ---------------------------------------------------------------------------
// combine_out: per ordered tile (b,i,j): v = mask(sum of 4 partials) * adj_v;
// out_partial[slot j][rows i*128..] = v @ HW[j-block]. grid = Bb*64 = 128.
// ---------------------------------------------------------------------------
#define CO_SMEM (128 * 132 * 4 + 128 * 68 * 4)

__global__ void __launch_bounds__(256, 1)
combine_out(const float* __restrict__ adj_v) {
    extern __shared__ float cs[];
    float* vs = cs;                      // [k][r] stride 132
    float* HWs = cs + 128 * 132;         // [k][d] stride 68

    int tid = threadIdx.x;
    int bid = blockIdx.x;
    int b = bid >> 6;
    int ij = bid & 63;
    int i = ij >> 3, j = ij & 7;

    const float* HWb = g_hw + (size_t)b * Nn * Dd + (size_t)j * 128 * 64;
    for (int idx = tid; idx < 8192; idx += 256)
        HWs[(idx >> 6) * 68 + (idx & 63)] = HWb[idx];

    int lo = i < j ? i : j, hi = i < j ? j : i;
    int p = 8 * lo - lo * (lo - 1) / 2 + (hi - lo);
    const float* p0 = g_part + ((size_t)(b * PAIRS8 + p) * 4 + 0) * 16384;
    const float* p1 = g_part + ((size_t)(b * PAIRS8 + p) * 4 + 1) * 16384;
    const float* p2 = g_part + ((size_t)(b * PAIRS8 + p) * 4 + 2) * 16384;
    const float* p3 = g_part + ((size_t)(b * PAIRS8 + p) * 4 + 3) * 16384;
    if (i <= j) {
        for (int idx = tid; idx < 16384; idx += 256) {
            int r = idx >> 7, c = idx & 127;
            vs[c * 132 + r] = (p0[idx] + p1[idx]) + (p2[idx] + p3[idx]);
        }
    } else {
        for (int idx = tid; idx < 16384; idx += 256) {
            int rp = idx >> 7, cp = idx & 127;
            vs[rp * 132 + cp] = (p0[idx] + p1[idx]) + (p2[idx] + p3[idx]);
        }
    }
    __syncthreads();

    const float* av = adj_v + (size_t)b * Nn * Nn;
    for (int idx = tid; idx < 16384; idx += 256) {
        int r = idx >> 7, c = idx & 127;
        int n = i * 128 + r, mcol = j * 128 + c;
        float m = vs[c * 132 + r];
        if (i == j && r == c) m = 1.f;
        vs[c * 132 + r] = m * av[(size_t)n * Nn + mcol];
    }
    __syncthreads();

    int rq = tid & 15;          // rows rq*8 .. +7
    int cq = tid >> 4;          // cols cq*4 .. +3
    float o[8][4];
#pragma unroll
    for (int r = 0; r < 8; r++)
#pragma unroll
        for (int c = 0; c < 4; c++) o[r][c] = 0.f;

    for (int k = 0; k < 128; k++) {
        float4 h = *reinterpret_cast<float4*>(&HWs[k * 68 + cq * 4]);
        float4 v0 = *reinterpret_cast<float4*>(&vs[k * 132 + rq * 8]);
        float4 v1 = *reinterpret_cast<float4*>(&vs[k * 132 + rq * 8 + 4]);
        float vv[8] = {v0.x, v0.y, v0.z, v0.w, v1.x, v1.y, v1.z, v1.w};
#pragma unroll
        for (int r = 0; r < 8; r++) {
            o[r][0] += vv[r] * h.x; o[r][1] += vv[r] * h.y;
            o[r][2] += vv[r] * h.z; o[r][3] += vv[r] * h.w;
        }
    }

    float* os = g_outp8[j] + ((size_t)b * Nn + i * 128) * 64;
#pragma unroll
    for (int r = 0; r < 8; r++)
        *reinterpret_cast<float4*>(&os[(size_t)(rq * 8 + r) * 64 + cq * 4]) =
            make_float4(o[r][0], o[r][1], o[r][2], o[r][3]);
}

// ---------------------------------------------------------------------------
__global__ void out_reduce(const float* __restrict__ bias, float* __restrict__ out) {
    int idx = blockIdx.x * 256 + threadIdx.x;
    if (idx < Bb * Nn * Dd) {
        float s = bias[idx & 63];
#pragma unroll
        for (int q = 0; q < NT8; q++) s += g_outp8[q][idx];
        out[idx] = s;
    }
}

// ---------------------------------------------------------------------------
extern "C" void kernel_launch(void* const* d_in, const int* in_sizes, int n_in,
                              void* d_out, int out_size) {
    const float* H_v   = (const float*)d_in[0];
    const float* H_e   = (const float*)d_in[1];
    // d_in[2] = adj_e : unused by the reference math
    const float* adj_v = (const float*)d_in[3];
    const float* T     = (const float*)d_in[4];
    const float* W     = (const float*)d_in[5];
    const float* p     = (const float*)d_in[6];
    const float* bias  = (const float*)d_in[7];
    float* out = (float*)d_out;

    static bool attr_set = false;
    if (!attr_set) {
        cudaFuncSetAttribute(mult_partial, cudaFuncAttributeMaxDynamicSharedMemorySize,
                             MULT_SMEM);
        cudaFuncSetAttribute(combine_out, cudaFuncAttributeMaxDynamicSharedMemorySize,
                             CO_SMEM);
        attr_set = true;
    }

    scale_kernel<<<(Bb * Ee + 255) / 256, 256>>>(H_e, p);
    hw_kernel<<<(Bb * Nn) / 4, dim3(64, 4)>>>(H_v, W);
    mult_partial<<<Bb * PAIRS8 * KSPLIT, 256, MULT_SMEM>>>(T);
    combine_out<<<Bb * NT8 * NT8, 256, CO_SMEM>>>(adj_v);
    out_reduce<<<(Bb * Nn * Dd + 255) / 256, 256>>>(bias, out);

    // Second tuple output: H_e pass-through, appended after `output`
    const long long out_elems = (long long)Bb * Nn * Dd;     // 131072
    const long long he_elems  = (long long)Bb * Ee * 64;     // 1048576
    if ((long long)out_size >= out_elems + he_elems) {
        cudaMemcpyAsync(out + out_elems, H_e,
                        (size_t)he_elems * sizeof(float),
                        cudaMemcpyDeviceToDevice, 0);
    }
}

// round 11
// speedup vs baseline: 1.1360x; 1.1360x over previous
#include <cuda_runtime.h>
#include <cuda_bf16.h>
#include <cstdint>

// Problem constants
#define Bb 2
#define Nn 1024
#define Ee 8192
#define Dd 64
#define NT8 8            // 8 tiles of 128 along N
#define PAIRS8 36        // upper-triangular tile pairs
#define KC 32            // K elements per stage
#define KSPLIT 4
#define KQ (Ee / KSPLIT)           // 2048
#define NCHUNK (KQ / KC)           // 64

// ---------------------------------------------------------------------------
// Device scratch
// ---------------------------------------------------------------------------
__device__ float g_scale[Bb * Ee];
__device__ float g_hw[Bb * Nn * Dd];
__device__ float g_part[(size_t)Bb * PAIRS8 * KSPLIT * 128 * 128];
__device__ float g_outp8[NT8][Bb * Nn * Dd];
__device__ float g_Atf[(size_t)Bb * Nn * Ee];   // rna_tf32(T*scale)

// ---------------------------------------------------------------------------
// Portable PTX helpers
// ---------------------------------------------------------------------------
__device__ __forceinline__ uint32_t smem_u32(const void* p) {
    uint32_t a;
    asm("{ .reg .u64 t; cvta.to.shared.u64 t, %1; cvt.u32.u64 %0, t; }" : "=r"(a) : "l"(p));
    return a;
}
#define CP16(dst, src) \
    asm volatile("cp.async.cg.shared.global [%0], [%1], 16;" :: "r"(dst), "l"(src))
#define CP_COMMIT() asm volatile("cp.async.commit_group;")
#define CP_WAIT0()  asm volatile("cp.async.wait_group 0;")
#define CP_WAIT1()  asm volatile("cp.async.wait_group 1;")

__device__ __forceinline__ uint32_t f2tf32(float x) {
    uint32_t r;
    asm("cvt.rna.tf32.f32 %0, %1;" : "=r"(r) : "f"(x));
    return r;
}
__device__ __forceinline__ void mma_tf32(float* c, const uint32_t* a, const uint32_t* b) {
    asm volatile(
        "mma.sync.aligned.m16n8k8.row.col.f32.tf32.tf32.f32 "
        "{%0,%1,%2,%3}, {%4,%5,%6,%7}, {%8,%9}, {%0,%1,%2,%3};"
        : "+f"(c[0]), "+f"(c[1]), "+f"(c[2]), "+f"(c[3])
        : "r"(a[0]), "r"(a[1]), "r"(a[2]), "r"(a[3]), "r"(b[0]), "r"(b[1]));
}

// ---------------------------------------------------------------------------
// scale[b,e] = dot(H_e[b,e,:], p)
// ---------------------------------------------------------------------------
__global__ void scale_kernel(const float* __restrict__ H_e,
                             const float* __restrict__ p) {
    __shared__ float ps[64];
    if (threadIdx.x < 64) ps[threadIdx.x] = p[threadIdx.x];
    __syncthreads();
    int r = blockIdx.x * blockDim.x + threadIdx.x;
    if (r < Bb * Ee) {
        const float4* he = reinterpret_cast<const float4*>(H_e + (size_t)r * 64);
        float s = 0.f;
#pragma unroll
        for (int i = 0; i < 16; i++) {
            float4 v = he[i];
            s += v.x * ps[i * 4 + 0] + v.y * ps[i * 4 + 1] +
                 v.z * ps[i * 4 + 2] + v.w * ps[i * 4 + 3];
        }
        g_scale[r] = s;
    }
}

// ---------------------------------------------------------------------------
// prep: A = rna_tf32(T*scale). (B side now feeds raw f32 T straight to the
// tensor core, which truncates to tf32 — no Btf array needed.)
// ---------------------------------------------------------------------------
__global__ void prep_kernel(const float* __restrict__ T) {
    size_t idx4 = ((size_t)blockIdx.x * blockDim.x + threadIdx.x) * 4;
    if (idx4 >= (size_t)Bb * Nn * Ee) return;
    int e0 = (int)(idx4 & 8191);
    int b = (int)(idx4 >> 23);                 // row>>10 where row = idx4>>13
    float4 t = *reinterpret_cast<const float4*>(T + idx4);
    float4 s = *reinterpret_cast<const float4*>(g_scale + b * Ee + e0);
    uint4 av;
    av.x = f2tf32(t.x * s.x); av.y = f2tf32(t.y * s.y);
    av.z = f2tf32(t.z * s.z); av.w = f2tf32(t.w * s.w);
    *reinterpret_cast<uint4*>(g_Atf + idx4) = av;
}

// ---------------------------------------------------------------------------
// HW[r,d] = dot(H_v[r,:], W[:,d])
// ---------------------------------------------------------------------------
__global__ void hw_kernel(const float* __restrict__ H_v,
                          const float* __restrict__ W) {
    __shared__ float ws[64 * 64];
    __shared__ float hv[4][64];
    int tx = threadIdx.x, ty = threadIdx.y;
    int tid = ty * 64 + tx;
    for (int i = tid; i < 64 * 64; i += 256) ws[i] = W[i];
    int row0 = blockIdx.x * 4;
    hv[ty][tx] = H_v[(size_t)(row0 + ty) * 64 + tx];
    __syncthreads();
    float acc = 0.f;
#pragma unroll
    for (int k = 0; k < 64; k++) acc += hv[ty][k] * ws[k * 64 + tx];
    g_hw[(size_t)(row0 + ty) * 64 + tx] = acc;
}

// ---------------------------------------------------------------------------
// mult partial: 128x128 tile, quarter-K per CTA, single-term tf32 m16n8k8.
// A tile from g_Atf (rna(T*s)); B tile raw f32 T (hardware rz->tf32).
// grid = Bb*PAIRS8*KSPLIT = 288 (~2 CTAs/SM), 256 threads, warp grid 2x4.
// Stride 36 words -> conflict-free scalar LDS (bank = 4*lrow + lcol = lid).
// ---------------------------------------------------------------------------
#define STRIDE_W 36
#define STAGE_WORDS (128 * STRIDE_W)           // per array: 4608 words
#define OFF_B_BYTES (STAGE_WORDS * 4)          // 18432
#define STAGE_BYTES (2 * STAGE_WORDS * 4)      // 36864
#define MULT_SMEM (3 * STAGE_BYTES)            // 110592

__global__ void __launch_bounds__(256, 2)
mult_partial(const float* __restrict__ T) {
    extern __shared__ __align__(16) char smraw[];
    uint32_t stg = smem_u32(smraw);
    const uint32_t* smw = reinterpret_cast<const uint32_t*>(smraw);

    int tid = threadIdx.x;
    int wid = tid >> 5;
    int lid = tid & 31;
    int wm = wid & 1;          // m-half (64 rows)
    int wn = wid >> 1;         // n-quarter (32 cols)

    int p2 = blockIdx.x;
    int pair = p2 >> 2;
    int ksp = p2 & 3;
    int b = pair / PAIRS8;
    int t = pair % PAIRS8;
    int ti = 0, rem = t;
    while (rem >= NT8 - ti) { rem -= NT8 - ti; ti++; }
    int tj = ti + rem;

    size_t rowA = (size_t)(b * Nn + ti * 128);
    size_t rowB = (size_t)(b * Nn + tj * 128);
    int kbase = ksp * KQ;

    auto load_stage = [&](int sidx, int k0) {
        uint32_t sb = stg + sidx * STAGE_BYTES;
#pragma unroll
        for (int i = 0; i < 4; i++) {
            int chunk = tid + i * 256;           // 0..1023
            int row = chunk >> 3, cc = chunk & 7;
            uint32_t d = (uint32_t)(row * (STRIDE_W * 4) + cc * 16);
            CP16(sb + d, g_Atf + (rowA + row) * (size_t)Ee + k0 + cc * 4);
            CP16(sb + OFF_B_BYTES + d, T + (rowB + row) * (size_t)Ee + k0 + cc * 4);
        }
        CP_COMMIT();
    };

    float acc[4][4][4];
#pragma unroll
    for (int i = 0; i < 4; i++)
#pragma unroll
        for (int j = 0; j < 4; j++)
#pragma unroll
            for (int q = 0; q < 4; q++) acc[i][j][q] = 0.f;

    load_stage(0, kbase);
    load_stage(1, kbase + KC);

    int lrow = lid >> 2;       // 0..7
    int lcol = lid & 3;        // 0..3

    for (int s = 0; s < NCHUNK; s++) {
        if (s < NCHUNK - 1) CP_WAIT1(); else CP_WAIT0();
        __syncthreads();
        const uint32_t* As = smw + (s % 3) * (STAGE_BYTES / 4);
        const uint32_t* Bs = As + STAGE_WORDS;

#pragma unroll
        for (int ks = 0; ks < 4; ks++) {
            int kc = ks * 8 + lcol;
            uint32_t af[4][4], bf[4][2];
#pragma unroll
            for (int mt = 0; mt < 4; mt++) {
                int rb = (wm * 64 + mt * 16 + lrow) * STRIDE_W;
                af[mt][0] = As[rb + kc];
                af[mt][1] = As[rb + 8 * STRIDE_W + kc];
                af[mt][2] = As[rb + kc + 4];
                af[mt][3] = As[rb + 8 * STRIDE_W + kc + 4];
            }
#pragma unroll
            for (int nt = 0; nt < 4; nt++) {
                int nb = (wn * 32 + nt * 8 + lrow) * STRIDE_W;
                bf[nt][0] = Bs[nb + kc];
                bf[nt][1] = Bs[nb + kc + 4];
            }
#pragma unroll
            for (int mt = 0; mt < 4; mt++)
#pragma unroll
                for (int nt = 0; nt < 4; nt++)
                    mma_tf32(acc[mt][nt], af[mt], bf[nt]);
        }
        if (s + 2 < NCHUNK) load_stage((s + 2) % 3, kbase + (s + 2) * KC);
    }

    // write partial tile
    float* pt = g_part + (size_t)p2 * 128 * 128;
#pragma unroll
    for (int mt = 0; mt < 4; mt++)
#pragma unroll
        for (int nt = 0; nt < 4; nt++) {
            int r = wm * 64 + mt * 16 + (lid >> 2);
            int c = wn * 32 + nt * 8 + (lid & 3) * 2;
            *reinterpret_cast<float2*>(pt + (size_t)r * 128 + c) =
                make_float2(acc[mt][nt][0], acc[mt][nt][1]);
            *reinterpret_cast<float2*>(pt + (size_t)(r + 8) * 128 + c) =
                make_float2(acc[mt][nt][2], acc[mt][nt][3]);
        }
}

// ---------------------------------------------------------------------------
// combine_out: per ordered tile (b,i,j): v = mask(sum of 4 partials) * adj_v;
// out_partial[slot j][rows i*128..] = v @ HW[j-block]. grid = Bb*64 = 128,
// 512 threads (4x4 outputs/thread) for latency hiding.
// ---------------------------------------------------------------------------
#define CO_SMEM (128 * 132 * 4 + 128 * 68 * 4)

__global__ void __launch_bounds__(512, 1)
combine_out(const float* __restrict__ adj_v) {
    extern __shared__ float cs[];
    float* vs = cs;                      // [k][r] stride 132
    float* HWs = cs + 128 * 132;         // [k][d] stride 68

    int tid = threadIdx.x;
    int bid = blockIdx.x;
    int b = bid >> 6;
    int ij = bid & 63;
    int i = ij >> 3, j = ij & 7;

    const float* HWb = g_hw + (size_t)b * Nn * Dd + (size_t)j * 128 * 64;
    for (int idx = tid; idx < 8192; idx += 512)
        HWs[(idx >> 6) * 68 + (idx & 63)] = HWb[idx];

    int lo = i < j ? i : j, hi = i < j ? j : i;
    int p = 8 * lo - lo * (lo - 1) / 2 + (hi - lo);
    const float* p0 = g_part + ((size_t)(b * PAIRS8 + p) * 4 + 0) * 16384;
    const float* p1 = g_part + ((size_t)(b * PAIRS8 + p) * 4 + 1) * 16384;
    const float* p2 = g_part + ((size_t)(b * PAIRS8 + p) * 4 + 2) * 16384;
    const float* p3 = g_part + ((size_t)(b * PAIRS8 + p) * 4 + 3) * 16384;
    if (i <= j) {
        for (int idx = tid; idx < 16384; idx += 512) {
            int r = idx >> 7, c = idx & 127;
            vs[c * 132 + r] = (p0[idx] + p1[idx]) + (p2[idx] + p3[idx]);
        }
    } else {
        for (int idx = tid; idx < 16384; idx += 512) {
            int rp = idx >> 7, cp = idx & 127;
            vs[rp * 132 + cp] = (p0[idx] + p1[idx]) + (p2[idx] + p3[idx]);
        }
    }
    __syncthreads();

    const float* av = adj_v + (size_t)b * Nn * Nn;
    for (int idx = tid; idx < 16384; idx += 512) {
        int r = idx >> 7, c = idx & 127;
        int n = i * 128 + r, mcol = j * 128 + c;
        float m = vs[c * 132 + r];
        if (i == j && r == c) m = 1.f;
        vs[c * 132 + r] = m * av[(size_t)n * Nn + mcol];
    }
    __syncthreads();

    int rq = tid & 31;          // rows rq*4 .. +3
    int cq = tid >> 5;          // cols cq*4 .. +3
    float o[4][4];
#pragma unroll
    for (int r = 0; r < 4; r++)
#pragma unroll
        for (int c = 0; c < 4; c++) o[r][c] = 0.f;

    for (int k = 0; k < 128; k++) {
        float4 h = *reinterpret_cast<float4*>(&HWs[k * 68 + cq * 4]);
        float4 v = *reinterpret_cast<float4*>(&vs[k * 132 + rq * 4]);
        float vv[4] = {v.x, v.y, v.z, v.w};
#pragma unroll
        for (int r = 0; r < 4; r++) {
            o[r][0] += vv[r] * h.x; o[r][1] += vv[r] * h.y;
            o[r][2] += vv[r] * h.z; o[r][3] += vv[r] * h.w;
        }
    }

    float* os = g_outp8[j] + ((size_t)b * Nn + i * 128) * 64;
#pragma unroll
    for (int r = 0; r < 4; r++)
        *reinterpret_cast<float4*>(&os[(size_t)(rq * 4 + r) * 64 + cq * 4]) =
            make_float4(o[r][0], o[r][1], o[r][2], o[r][3]);
}

// ---------------------------------------------------------------------------
__global__ void out_reduce(const float* __restrict__ bias, float* __restrict__ out) {
    int idx = blockIdx.x * 256 + threadIdx.x;
    if (idx < Bb * Nn * Dd) {
        float s = bias[idx & 63];
#pragma unroll
        for (int q = 0; q < NT8; q++) s += g_outp8[q][idx];
        out[idx] = s;
    }
}

// ---------------------------------------------------------------------------
extern "C" void kernel_launch(void* const* d_in, const int* in_sizes, int n_in,
                              void* d_out, int out_size) {
    const float* H_v   = (const float*)d_in[0];
    const float* H_e   = (const float*)d_in[1];
    // d_in[2] = adj_e : unused by the reference math
    const float* adj_v = (const float*)d_in[3];
    const float* T     = (const float*)d_in[4];
    const float* W     = (const float*)d_in[5];
    const float* p     = (const float*)d_in[6];
    const float* bias  = (const float*)d_in[7];
    float* out = (float*)d_out;

    static bool attr_set = false;
    if (!attr_set) {
        cudaFuncSetAttribute(mult_partial, cudaFuncAttributeMaxDynamicSharedMemorySize,
                             MULT_SMEM);
        cudaFuncSetAttribute(combine_out, cudaFuncAttributeMaxDynamicSharedMemorySize,
                             CO_SMEM);
        attr_set = true;
    }

    scale_kernel<<<(Bb * Ee + 255) / 256, 256>>>(H_e, p);
    prep_kernel<<<(Bb * Nn * Ee / 4 + 255) / 256, 256>>>(T);
    hw_kernel<<<(Bb * Nn) / 4, dim3(64, 4)>>>(H_v, W);
    mult_partial<<<Bb * PAIRS8 * KSPLIT, 256, MULT_SMEM>>>(T);
    combine_out<<<Bb * NT8 * NT8, 512, CO_SMEM>>>(adj_v);
    out_reduce<<<(Bb * Nn * Dd + 255) / 256, 256>>>(bias, out);

    // Second tuple output: H_e pass-through, appended after `output`
    const long long out_elems = (long long)Bb * Nn * Dd;     // 131072
    const long long he_elems  = (long long)Bb * Ee * 64;     // 1048576
    if ((long long)out_size >= out_elems + he_elems) {
        cudaMemcpyAsync(out + out_elems, H_e,
                        (size_t)he_elems * sizeof(float),
                        cudaMemcpyDeviceToDevice, 0);
    }
}

// round 12
// speedup vs baseline: 1.2129x; 1.0677x over previous
#include <cuda_runtime.h>
#include <cuda_bf16.h>
#include <cstdint>

// Problem constants
#define Bb 2
#define Nn 1024
#define Ee 8192
#define Dd 64
#define NT8 8            // 8 tiles of 128 along N
#define PAIRS8 36        // upper-triangular tile pairs
#define KC 32            // K elements per stage
#define KSPLIT 4
#define KQ (Ee / KSPLIT)           // 2048
#define NCHUNK (KQ / KC)           // 64

// ---------------------------------------------------------------------------
// Device scratch
// ---------------------------------------------------------------------------
__device__ float g_scale[Bb * Ee];
__device__ float g_hw[Bb * Nn * Dd];
__device__ float g_part[(size_t)Bb * PAIRS8 * KSPLIT * 128 * 128];
__device__ float g_outp8[NT8][Bb * Nn * Dd];
__device__ float g_Atf[(size_t)Bb * Nn * Ee];   // rna_tf32(T*scale)

// ---------------------------------------------------------------------------
// Portable PTX helpers
// ---------------------------------------------------------------------------
__device__ __forceinline__ uint32_t smem_u32(const void* p) {
    uint32_t a;
    asm("{ .reg .u64 t; cvta.to.shared.u64 t, %1; cvt.u32.u64 %0, t; }" : "=r"(a) : "l"(p));
    return a;
}
#define CP16(dst, src) \
    asm volatile("cp.async.cg.shared.global [%0], [%1], 16;" :: "r"(dst), "l"(src))
#define CP_COMMIT() asm volatile("cp.async.commit_group;")
#define CP_WAIT0()  asm volatile("cp.async.wait_group 0;")
#define CP_WAIT1()  asm volatile("cp.async.wait_group 1;")

__device__ __forceinline__ uint32_t f2tf32(float x) {
    uint32_t r;
    asm("cvt.rna.tf32.f32 %0, %1;" : "=r"(r) : "f"(x));
    return r;
}
__device__ __forceinline__ void ldsm4(uint32_t* r, uint32_t addr) {
    asm volatile("ldmatrix.sync.aligned.m8n8.x4.shared.b16 {%0,%1,%2,%3}, [%4];"
                 : "=r"(r[0]), "=r"(r[1]), "=r"(r[2]), "=r"(r[3]) : "r"(addr));
}
__device__ __forceinline__ void mma_tf32(float* c, const uint32_t* a, const uint32_t* b) {
    asm volatile(
        "mma.sync.aligned.m16n8k8.row.col.f32.tf32.tf32.f32 "
        "{%0,%1,%2,%3}, {%4,%5,%6,%7}, {%8,%9}, {%0,%1,%2,%3};"
        : "+f"(c[0]), "+f"(c[1]), "+f"(c[2]), "+f"(c[3])
        : "r"(a[0]), "r"(a[1]), "r"(a[2]), "r"(a[3]), "r"(b[0]), "r"(b[1]));
}

// ---------------------------------------------------------------------------
// scale[b,e] = dot(H_e[b,e,:], p)
// ---------------------------------------------------------------------------
__global__ void scale_kernel(const float* __restrict__ H_e,
                             const float* __restrict__ p) {
    __shared__ float ps[64];
    if (threadIdx.x < 64) ps[threadIdx.x] = p[threadIdx.x];
    __syncthreads();
    int r = blockIdx.x * blockDim.x + threadIdx.x;
    if (r < Bb * Ee) {
        const float4* he = reinterpret_cast<const float4*>(H_e + (size_t)r * 64);
        float s = 0.f;
#pragma unroll
        for (int i = 0; i < 16; i++) {
            float4 v = he[i];
            s += v.x * ps[i * 4 + 0] + v.y * ps[i * 4 + 1] +
                 v.z * ps[i * 4 + 2] + v.w * ps[i * 4 + 3];
        }
        g_scale[r] = s;
    }
}

// ---------------------------------------------------------------------------
// prep: A = rna_tf32(T*scale). B side feeds raw f32 T (hw rz->tf32).
// ---------------------------------------------------------------------------
__global__ void prep_kernel(const float* __restrict__ T) {
    size_t idx4 = ((size_t)blockIdx.x * blockDim.x + threadIdx.x) * 4;
    if (idx4 >= (size_t)Bb * Nn * Ee) return;
    int e0 = (int)(idx4 & 8191);
    int b = (int)(idx4 >> 23);
    float4 t = *reinterpret_cast<const float4*>(T + idx4);
    float4 s = *reinterpret_cast<const float4*>(g_scale + b * Ee + e0);
    uint4 av;
    av.x = f2tf32(t.x * s.x); av.y = f2tf32(t.y * s.y);
    av.z = f2tf32(t.z * s.z); av.w = f2tf32(t.w * s.w);
    *reinterpret_cast<uint4*>(g_Atf + idx4) = av;
}

// ---------------------------------------------------------------------------
// HW[r,d] = dot(H_v[r,:], W[:,d])
// ---------------------------------------------------------------------------
__global__ void hw_kernel(const float* __restrict__ H_v,
                          const float* __restrict__ W) {
    __shared__ float ws[64 * 64];
    __shared__ float hv[4][64];
    int tx = threadIdx.x, ty = threadIdx.y;
    int tid = ty * 64 + tx;
    for (int i = tid; i < 64 * 64; i += 256) ws[i] = W[i];
    int row0 = blockIdx.x * 4;
    hv[ty][tx] = H_v[(size_t)(row0 + ty) * 64 + tx];
    __syncthreads();
    float acc = 0.f;
#pragma unroll
    for (int k = 0; k < 64; k++) acc += hv[ty][k] * ws[k * 64 + tx];
    g_hw[(size_t)(row0 + ty) * 64 + tx] = acc;
}

// ---------------------------------------------------------------------------
// mult partial: 128x128 tile, quarter-K per CTA, single-term tf32 m16n8k8.
// Fragment loads via ldmatrix.b16 (f32 = b16 pair): m8n8-b16 matrix = 8 rows
// x 4 f32-cols, delivered element (row=lane>>2, f32col=lane&3) == tf32
// fragment layout. 24 ldmatrix.x4 per warp-chunk replaces 96 scalar LDS.
// Stride 36 words: 8-row phases hit word-banks 4r..4r+3 -> conflict-free.
// grid = Bb*PAIRS8*KSPLIT = 288 (~2 CTAs/SM), 256 threads, warp grid 2x4.
// ---------------------------------------------------------------------------
#define STRIDE_W 36
#define STAGE_WORDS (128 * STRIDE_W)           // per array: 4608 words
#define OFF_B_BYTES (STAGE_WORDS * 4)          // 18432
#define STAGE_BYTES (2 * STAGE_WORDS * 4)      // 36864
#define MULT_SMEM (3 * STAGE_BYTES)            // 110592
#define ROWB (STRIDE_W * 4)                    // 144 bytes per row
#define MTSTEP (16 * ROWB)                     // 2304 bytes per 16-row block

__global__ void __launch_bounds__(256, 2)
mult_partial(const float* __restrict__ T) {
    extern __shared__ __align__(16) char smraw[];
    uint32_t stg = smem_u32(smraw);

    int tid = threadIdx.x;
    int wid = tid >> 5;
    int lid = tid & 31;
    int wm = wid & 1;          // m-half (64 rows)
    int wn = wid >> 1;         // n-quarter (32 cols)

    int p2 = blockIdx.x;
    int pair = p2 >> 2;
    int ksp = p2 & 3;
    int b = pair / PAIRS8;
    int t = pair % PAIRS8;
    int ti = 0, rem = t;
    while (rem >= NT8 - ti) { rem -= NT8 - ti; ti++; }
    int tj = ti + rem;

    size_t rowA = (size_t)(b * Nn + ti * 128);
    size_t rowB = (size_t)(b * Nn + tj * 128);
    int kbase = ksp * KQ;

    auto load_stage = [&](int sidx, int k0) {
        uint32_t sb = stg + sidx * STAGE_BYTES;
#pragma unroll
        for (int i = 0; i < 4; i++) {
            int chunk = tid + i * 256;           // 0..1023
            int row = chunk >> 3, cc = chunk & 7;
            uint32_t d = (uint32_t)(row * ROWB + cc * 16);
            CP16(sb + d, g_Atf + (rowA + row) * (size_t)Ee + k0 + cc * 4);
            CP16(sb + OFF_B_BYTES + d, T + (rowB + row) * (size_t)Ee + k0 + cc * 4);
        }
        CP_COMMIT();
    };

    float acc[4][4][4];
#pragma unroll
    for (int i = 0; i < 4; i++)
#pragma unroll
        for (int j = 0; j < 4; j++)
#pragma unroll
            for (int q = 0; q < 4; q++) acc[i][j][q] = 0.f;

    load_stage(0, kbase);
    load_stage(1, kbase + KC);

    // Per-lane ldmatrix source offsets (byte offsets within a stage).
    // A x4: matrices {rows r0..+7 | r0+8..+15} x {cols +0..3 | +4..7}
    uint32_t a_lane = (uint32_t)(((lid & 7) + ((lid >> 3) & 1) * 8) * ROWB +
                                 (lid >> 4) * 16);
    // B x4: matrices {b0(nt even), b1(even), b0(odd), b1(odd)}
    //   mIdx = lid>>3: row = (mIdx>>1)*8 + (lid&7), col = (mIdx&1)*4
    uint32_t b_lane = (uint32_t)((((lid >> 4) * 8) + (lid & 7)) * ROWB +
                                 (((lid >> 3) & 1) * 16));
    uint32_t a_base0 = (uint32_t)(wm * 64 * ROWB) + a_lane;
    uint32_t b_base0 = (uint32_t)OFF_B_BYTES + (uint32_t)(wn * 32 * ROWB) + b_lane;

    for (int s = 0; s < NCHUNK; s++) {
        if (s < NCHUNK - 1) CP_WAIT1(); else CP_WAIT0();
        __syncthreads();
        uint32_t sb = stg + (s % 3) * STAGE_BYTES;
        uint32_t ab = sb + a_base0;
        uint32_t bb = sb + b_base0;

#pragma unroll
        for (int ks = 0; ks < 4; ks++) {
            uint32_t af[4][4], bq[2][4];
#pragma unroll
            for (int mt = 0; mt < 4; mt++)
                ldsm4(af[mt], ab + mt * MTSTEP + ks * 32);
#pragma unroll
            for (int ntp = 0; ntp < 2; ntp++)
                ldsm4(bq[ntp], bb + ntp * MTSTEP + ks * 32);
#pragma unroll
            for (int mt = 0; mt < 4; mt++)
#pragma unroll
                for (int nt = 0; nt < 4; nt++)
                    mma_tf32(acc[mt][nt], af[mt], &bq[nt >> 1][(nt & 1) * 2]);
        }
        if (s + 2 < NCHUNK) load_stage((s + 2) % 3, kbase + (s + 2) * KC);
    }

    // write partial tile
    float* pt = g_part + (size_t)p2 * 128 * 128;
#pragma unroll
    for (int mt = 0; mt < 4; mt++)
#pragma unroll
        for (int nt = 0; nt < 4; nt++) {
            int r = wm * 64 + mt * 16 + (lid >> 2);
            int c = wn * 32 + nt * 8 + (lid & 3) * 2;
            *reinterpret_cast<float2*>(pt + (size_t)r * 128 + c) =
                make_float2(acc[mt][nt][0], acc[mt][nt][1]);
            *reinterpret_cast<float2*>(pt + (size_t)(r + 8) * 128 + c) =
                make_float2(acc[mt][nt][2], acc[mt][nt][3]);
        }
}

// ---------------------------------------------------------------------------
// combine_out: per ordered tile (b,i,j): v = mask(sum of 4 partials) * adj_v;
// out_partial[slot j][rows i*128..] = v @ HW[j-block]. grid = Bb*64 = 128,
// 512 threads (4x4 outputs/thread).
// ---------------------------------------------------------------------------
#define CO_SMEM (128 * 132 * 4 + 128 * 68 * 4)

__global__ void __launch_bounds__(512, 1)
combine_out(const float* __restrict__ adj_v) {
    extern __shared__ float cs[];
    float* vs = cs;                      // [k][r] stride 132
    float* HWs = cs + 128 * 132;         // [k][d] stride 68

    int tid = threadIdx.x;
    int bid = blockIdx.x;
    int b = bid >> 6;
    int ij = bid & 63;
    int i = ij >> 3, j = ij & 7;

    const float* HWb = g_hw + (size_t)b * Nn * Dd + (size_t)j * 128 * 64;
    for (int idx = tid; idx < 8192; idx += 512)
        HWs[(idx >> 6) * 68 + (idx & 63)] = HWb[idx];

    int lo = i < j ? i : j, hi = i < j ? j : i;
    int p = 8 * lo - lo * (lo - 1) / 2 + (hi - lo);
    const float* p0 = g_part + ((size_t)(b * PAIRS8 + p) * 4 + 0) * 16384;
    const float* p1 = g_part + ((size_t)(b * PAIRS8 + p) * 4 + 1) * 16384;
    const float* p2 = g_part + ((size_t)(b * PAIRS8 + p) * 4 + 2) * 16384;
    const float* p3 = g_part + ((size_t)(b * PAIRS8 + p) * 4 + 3) * 16384;
    if (i <= j) {
        for (int idx = tid; idx < 16384; idx += 512) {
            int r = idx >> 7, c = idx & 127;
            vs[c * 132 + r] = (p0[idx] + p1[idx]) + (p2[idx] + p3[idx]);
        }
    } else {
        for (int idx = tid; idx < 16384; idx += 512) {
            int rp = idx >> 7, cp = idx & 127;
            vs[rp * 132 + cp] = (p0[idx] + p1[idx]) + (p2[idx] + p3[idx]);
        }
    }
    __syncthreads();

    const float* av = adj_v + (size_t)b * Nn * Nn;
    for (int idx = tid; idx < 16384; idx += 512) {
        int r = idx >> 7, c = idx & 127;
        int n = i * 128 + r, mcol = j * 128 + c;
        float m = vs[c * 132 + r];
        if (i == j && r == c) m = 1.f;
        vs[c * 132 + r] = m * av[(size_t)n * Nn + mcol];
    }
    __syncthreads();

    int rq = tid & 31;          // rows rq*4 .. +3
    int cq = tid >> 5;          // cols cq*4 .. +3
    float o[4][4];
#pragma unroll
    for (int r = 0; r < 4; r++)
#pragma unroll
        for (int c = 0; c < 4; c++) o[r][c] = 0.f;

    for (int k = 0; k < 128; k++) {
        float4 h = *reinterpret_cast<float4*>(&HWs[k * 68 + cq * 4]);
        float4 v = *reinterpret_cast<float4*>(&vs[k * 132 + rq * 4]);
        float vv[4] = {v.x, v.y, v.z, v.w};
#pragma unroll
        for (int r = 0; r < 4; r++) {
            o[r][0] += vv[r] * h.x; o[r][1] += vv[r] * h.y;
            o[r][2] += vv[r] * h.z; o[r][3] += vv[r] * h.w;
        }
    }

    float* os = g_outp8[j] + ((size_t)b * Nn + i * 128) * 64;
#pragma unroll
    for (int r = 0; r < 4; r++)
        *reinterpret_cast<float4*>(&os[(size_t)(rq * 4 + r) * 64 + cq * 4]) =
            make_float4(o[r][0], o[r][1], o[r][2], o[r][3]);
}

// ---------------------------------------------------------------------------
__global__ void out_reduce(const float* __restrict__ bias, float* __restrict__ out) {
    int idx = blockIdx.x * 256 + threadIdx.x;
    if (idx < Bb * Nn * Dd) {
        float s = bias[idx & 63];
#pragma unroll
        for (int q = 0; q < NT8; q++) s += g_outp8[q][idx];
        out[idx] = s;
    }
}

// ---------------------------------------------------------------------------
extern "C" void kernel_launch(void* const* d_in, const int* in_sizes, int n_in,
                              void* d_out, int out_size) {
    const float* H_v   = (const float*)d_in[0];
    const float* H_e   = (const float*)d_in[1];
    // d_in[2] = adj_e : unused by the reference math
    const float* adj_v = (const float*)d_in[3];
    const float* T     = (const float*)d_in[4];
    const float* W     = (const float*)d_in[5];
    const float* p     = (const float*)d_in[6];
    const float* bias  = (const float*)d_in[7];
    float* out = (float*)d_out;

    static bool attr_set = false;
    if (!attr_set) {
        cudaFuncSetAttribute(mult_partial, cudaFuncAttributeMaxDynamicSharedMemorySize,
                             MULT_SMEM);
        cudaFuncSetAttribute(combine_out, cudaFuncAttributeMaxDynamicSharedMemorySize,
                             CO_SMEM);
        attr_set = true;
    }

    scale_kernel<<<(Bb * Ee + 255) / 256, 256>>>(H_e, p);
    prep_kernel<<<(Bb * Nn * Ee / 4 + 255) / 256, 256>>>(T);
    hw_kernel<<<(Bb * Nn) / 4, dim3(64, 4)>>>(H_v, W);
    mult_partial<<<Bb * PAIRS8 * KSPLIT, 256, MULT_SMEM>>>(T);
    combine_out<<<Bb * NT8 * NT8, 512, CO_SMEM>>>(adj_v);
    out_reduce<<<(Bb * Nn * Dd + 255) / 256, 256>>>(bias, out);

    // Second tuple output: H_e pass-through, appended after `output`
    const long long out_elems = (long long)Bb * Nn * Dd;     // 131072
    const long long he_elems  = (long long)Bb * Ee * 64;     // 1048576
    if ((long long)out_size >= out_elems + he_elems) {
        cudaMemcpyAsync(out + out_elems, H_e,
                        (size_t)he_elems * sizeof(float),
                        cudaMemcpyDeviceToDevice, 0);
    }
}

// round 13
// speedup vs baseline: 1.2771x; 1.0530x over previous
#include <cuda_runtime.h>
#include <cuda_bf16.h>
#include <cstdint>

// Problem constants
#define Bb 2
#define Nn 1024
#define Ee 8192
#define Dd 64
#define NT8 8            // 8 tiles of 128 along N
#define PAIRS8 36        // upper-triangular tile pairs
#define KC 32            // K elements per stage
#define KSPLIT 4
#define KQ (Ee / KSPLIT)           // 2048
#define NCHUNK (KQ / KC)           // 64

// ---------------------------------------------------------------------------
// Device scratch
// ---------------------------------------------------------------------------
__device__ float g_scale[Bb * Ee];
__device__ float g_hw[Bb * Nn * Dd];
__device__ float g_part[(size_t)Bb * PAIRS8 * KSPLIT * 128 * 128];
__device__ float g_outp8[NT8][Bb * Nn * Dd];

// ---------------------------------------------------------------------------
// Portable PTX helpers
// ---------------------------------------------------------------------------
__device__ __forceinline__ uint32_t smem_u32(const void* p) {
    uint32_t a;
    asm("{ .reg .u64 t; cvta.to.shared.u64 t, %1; cvt.u32.u64 %0, t; }" : "=r"(a) : "l"(p));
    return a;
}
#define CP16(dst, src) \
    asm volatile("cp.async.cg.shared.global [%0], [%1], 16;" :: "r"(dst), "l"(src))
#define CP_COMMIT() asm volatile("cp.async.commit_group;")
#define CP_WAIT0()  asm volatile("cp.async.wait_group 0;")
#define CP_WAIT1()  asm volatile("cp.async.wait_group 1;")

__device__ __forceinline__ void ldsm4(uint32_t* r, uint32_t addr) {
    asm volatile("ldmatrix.sync.aligned.m8n8.x4.shared.b16 {%0,%1,%2,%3}, [%4];"
                 : "=r"(r[0]), "=r"(r[1]), "=r"(r[2]), "=r"(r[3]) : "r"(addr));
}
__device__ __forceinline__ void mma_tf32(float* c, const uint32_t* a, const uint32_t* b) {
    asm volatile(
        "mma.sync.aligned.m16n8k8.row.col.f32.tf32.tf32.f32 "
        "{%0,%1,%2,%3}, {%4,%5,%6,%7}, {%8,%9}, {%0,%1,%2,%3};"
        : "+f"(c[0]), "+f"(c[1]), "+f"(c[2]), "+f"(c[3])
        : "r"(a[0]), "r"(a[1]), "r"(a[2]), "r"(a[3]), "r"(b[0]), "r"(b[1]));
}

// ---------------------------------------------------------------------------
// scale[b,e] = dot(H_e[b,e,:], p)
// ---------------------------------------------------------------------------
__global__ void scale_kernel(const float* __restrict__ H_e,
                             const float* __restrict__ p) {
    __shared__ float ps[64];
    if (threadIdx.x < 64) ps[threadIdx.x] = p[threadIdx.x];
    __syncthreads();
    int r = blockIdx.x * blockDim.x + threadIdx.x;
    if (r < Bb * Ee) {
        const float4* he = reinterpret_cast<const float4*>(H_e + (size_t)r * 64);
        float s = 0.f;
#pragma unroll
        for (int i = 0; i < 16; i++) {
            float4 v = he[i];
            s += v.x * ps[i * 4 + 0] + v.y * ps[i * 4 + 1] +
                 v.z * ps[i * 4 + 2] + v.w * ps[i * 4 + 3];
        }
        g_scale[r] = s;
    }
}

// ---------------------------------------------------------------------------
// HW[r,d] = dot(H_v[r,:], W[:,d])
// ---------------------------------------------------------------------------
__global__ void hw_kernel(const float* __restrict__ H_v,
                          const float* __restrict__ W) {
    __shared__ float ws[64 * 64];
    __shared__ float hv[4][64];
    int tx = threadIdx.x, ty = threadIdx.y;
    int tid = ty * 64 + tx;
    for (int i = tid; i < 64 * 64; i += 256) ws[i] = W[i];
    int row0 = blockIdx.x * 4;
    hv[ty][tx] = H_v[(size_t)(row0 + ty) * 64 + tx];
    __syncthreads();
    float acc = 0.f;
#pragma unroll
    for (int k = 0; k < 64; k++) acc += hv[ty][k] * ws[k * 64 + tx];
    g_hw[(size_t)(row0 + ty) * 64 + tx] = acc;
}

// ---------------------------------------------------------------------------
// mult partial: 128x128 tile, quarter-K per CTA, single-term tf32 m16n8k8.
// Both tiles load RAW f32 T. The per-k scale is applied to the A fragments
// IN REGISTERS (s block staged per stage; a0/a1 carry k=ks*8+(lane&3),
// a2/a3 carry k+4). Hardware rz->tf32 truncation on both operands.
// No prep kernel, no Atf array.
// Fragment loads via ldmatrix.b16 (f32 = b16 pair), R12-proven mapping.
// grid = Bb*PAIRS8*KSPLIT = 288 (~2 CTAs/SM), 256 threads, warp grid 2x4.
// ---------------------------------------------------------------------------
#define STRIDE_W 36
#define STAGE_WORDS (128 * STRIDE_W)           // per array: 4608 words
#define OFF_B_BYTES (STAGE_WORDS * 4)          // 18432
#define OFF_S_BYTES (2 * STAGE_WORDS * 4)      // 36864 (32-float s block)
#define STAGE_BYTES (OFF_S_BYTES + 128)        // 36992
#define MULT_SMEM (3 * STAGE_BYTES)            // 110976 (x2 CTAs = 221952 OK)
#define ROWB (STRIDE_W * 4)                    // 144 bytes per row
#define MTSTEP (16 * ROWB)                     // 2304 bytes per 16-row block

__global__ void __launch_bounds__(256, 2)
mult_partial(const float* __restrict__ T) {
    extern __shared__ __align__(16) char smraw[];
    uint32_t stg = smem_u32(smraw);

    int tid = threadIdx.x;
    int wid = tid >> 5;
    int lid = tid & 31;
    int wm = wid & 1;          // m-half (64 rows)
    int wn = wid >> 1;         // n-quarter (32 cols)

    int p2 = blockIdx.x;
    int pair = p2 >> 2;
    int ksp = p2 & 3;
    int b = pair / PAIRS8;
    int t = pair % PAIRS8;
    int ti = 0, rem = t;
    while (rem >= NT8 - ti) { rem -= NT8 - ti; ti++; }
    int tj = ti + rem;

    size_t rowA = (size_t)(b * Nn + ti * 128);
    size_t rowB = (size_t)(b * Nn + tj * 128);
    int kbase = ksp * KQ;
    const float* scg = g_scale + b * Ee;       // index with absolute k0

    auto load_stage = [&](int sidx, int k0) {
        uint32_t sb = stg + sidx * STAGE_BYTES;
#pragma unroll
        for (int i = 0; i < 4; i++) {
            int chunk = tid + i * 256;           // 0..1023
            int row = chunk >> 3, cc = chunk & 7;
            uint32_t d = (uint32_t)(row * ROWB + cc * 16);
            CP16(sb + d, T + (rowA + row) * (size_t)Ee + k0 + cc * 4);
            CP16(sb + OFF_B_BYTES + d, T + (rowB + row) * (size_t)Ee + k0 + cc * 4);
        }
        if (tid < 8)
            CP16(sb + OFF_S_BYTES + tid * 16, scg + k0 + tid * 4);
        CP_COMMIT();
    };

    float acc[4][4][4];
#pragma unroll
    for (int i = 0; i < 4; i++)
#pragma unroll
        for (int j = 0; j < 4; j++)
#pragma unroll
            for (int q = 0; q < 4; q++) acc[i][j][q] = 0.f;

    load_stage(0, kbase);
    load_stage(1, kbase + KC);

    // Per-lane ldmatrix source offsets (R12-proven mapping).
    uint32_t a_lane = (uint32_t)(((lid & 7) + ((lid >> 3) & 1) * 8) * ROWB +
                                 (lid >> 4) * 16);
    uint32_t b_lane = (uint32_t)((((lid >> 4) * 8) + (lid & 7)) * ROWB +
                                 (((lid >> 3) & 1) * 16));
    uint32_t a_base0 = (uint32_t)(wm * 64 * ROWB) + a_lane;
    uint32_t b_base0 = (uint32_t)OFF_B_BYTES + (uint32_t)(wn * 32 * ROWB) + b_lane;
    int skc = lid & 3;         // k sub-index for this lane's a-fragments

    for (int s = 0; s < NCHUNK; s++) {
        if (s < NCHUNK - 1) CP_WAIT1(); else CP_WAIT0();
        __syncthreads();
        uint32_t sb = stg + (s % 3) * STAGE_BYTES;
        uint32_t ab = sb + a_base0;
        uint32_t bb = sb + b_base0;
        const float* sS = reinterpret_cast<const float*>(
            smraw + (size_t)(sb - stg) + OFF_S_BYTES);

#pragma unroll
        for (int ks = 0; ks < 4; ks++) {
            float sv0 = sS[ks * 8 + skc];        // broadcast LDS
            float sv1 = sS[ks * 8 + 4 + skc];
            uint32_t af[4][4], bq[2][4];
#pragma unroll
            for (int mt = 0; mt < 4; mt++)
                ldsm4(af[mt], ab + mt * MTSTEP + ks * 32);
#pragma unroll
            for (int ntp = 0; ntp < 2; ntp++)
                ldsm4(bq[ntp], bb + ntp * MTSTEP + ks * 32);
            // scale A fragments in registers (k per reg: 0,1 -> sv0; 2,3 -> sv1)
#pragma unroll
            for (int mt = 0; mt < 4; mt++) {
                af[mt][0] = __float_as_uint(__uint_as_float(af[mt][0]) * sv0);
                af[mt][1] = __float_as_uint(__uint_as_float(af[mt][1]) * sv0);
                af[mt][2] = __float_as_uint(__uint_as_float(af[mt][2]) * sv1);
                af[mt][3] = __float_as_uint(__uint_as_float(af[mt][3]) * sv1);
            }
#pragma unroll
            for (int mt = 0; mt < 4; mt++)
#pragma unroll
                for (int nt = 0; nt < 4; nt++)
                    mma_tf32(acc[mt][nt], af[mt], &bq[nt >> 1][(nt & 1) * 2]);
        }
        if (s + 2 < NCHUNK) load_stage((s + 2) % 3, kbase + (s + 2) * KC);
    }

    // write partial tile
    float* pt = g_part + (size_t)p2 * 128 * 128;
#pragma unroll
    for (int mt = 0; mt < 4; mt++)
#pragma unroll
        for (int nt = 0; nt < 4; nt++) {
            int r = wm * 64 + mt * 16 + (lid >> 2);
            int c = wn * 32 + nt * 8 + (lid & 3) * 2;
            *reinterpret_cast<float2*>(pt + (size_t)r * 128 + c) =
                make_float2(acc[mt][nt][0], acc[mt][nt][1]);
            *reinterpret_cast<float2*>(pt + (size_t)(r + 8) * 128 + c) =
                make_float2(acc[mt][nt][2], acc[mt][nt][3]);
        }
}

// ---------------------------------------------------------------------------
// combine_out: per ordered tile (b,i,j): v = mask(sum of 4 partials) * adj_v;
// out_partial[slot j][rows i*128..] = v @ HW[j-block]. grid = Bb*64 = 128,
// 512 threads (4x4 outputs/thread).
// ---------------------------------------------------------------------------
#define CO_SMEM (128 * 132 * 4 + 128 * 68 * 4)

__global__ void __launch_bounds__(512, 1)
combine_out(const float* __restrict__ adj_v) {
    extern __shared__ float cs[];
    float* vs = cs;                      // [k][r] stride 132
    float* HWs = cs + 128 * 132;         // [k][d] stride 68

    int tid = threadIdx.x;
    int bid = blockIdx.x;
    int b = bid >> 6;
    int ij = bid & 63;
    int i = ij >> 3, j = ij & 7;

    const float* HWb = g_hw + (size_t)b * Nn * Dd + (size_t)j * 128 * 64;
    for (int idx = tid; idx < 8192; idx += 512)
        HWs[(idx >> 6) * 68 + (idx & 63)] = HWb[idx];

    int lo = i < j ? i : j, hi = i < j ? j : i;
    int p = 8 * lo - lo * (lo - 1) / 2 + (hi - lo);
    const float* p0 = g_part + ((size_t)(b * PAIRS8 + p) * 4 + 0) * 16384;
    const float* p1 = g_part + ((size_t)(b * PAIRS8 + p) * 4 + 1) * 16384;
    const float* p2 = g_part + ((size_t)(b * PAIRS8 + p) * 4 + 2) * 16384;
    const float* p3 = g_part + ((size_t)(b * PAIRS8 + p) * 4 + 3) * 16384;
    if (i <= j) {
        for (int idx = tid; idx < 16384; idx += 512) {
            int r = idx >> 7, c = idx & 127;
            vs[c * 132 + r] = (p0[idx] + p1[idx]) + (p2[idx] + p3[idx]);
        }
    } else {
        for (int idx = tid; idx < 16384; idx += 512) {
            int rp = idx >> 7, cp = idx & 127;
            vs[rp * 132 + cp] = (p0[idx] + p1[idx]) + (p2[idx] + p3[idx]);
        }
    }
    __syncthreads();

    const float* av = adj_v + (size_t)b * Nn * Nn;
    for (int idx = tid; idx < 16384; idx += 512) {
        int r = idx >> 7, c = idx & 127;
        int n = i * 128 + r, mcol = j * 128 + c;
        float m = vs[c * 132 + r];
        if (i == j && r == c) m = 1.f;
        vs[c * 132 + r] = m * av[(size_t)n * Nn + mcol];
    }
    __syncthreads();

    int rq = tid & 31;          // rows rq*4 .. +3
    int cq = tid >> 5;          // cols cq*4 .. +3
    float o[4][4];
#pragma unroll
    for (int r = 0; r < 4; r++)
#pragma unroll
        for (int c = 0; c < 4; c++) o[r][c] = 0.f;

    for (int k = 0; k < 128; k++) {
        float4 h = *reinterpret_cast<float4*>(&HWs[k * 68 + cq * 4]);
        float4 v = *reinterpret_cast<float4*>(&vs[k * 132 + rq * 4]);
        float vv[4] = {v.x, v.y, v.z, v.w};
#pragma unroll
        for (int r = 0; r < 4; r++) {
            o[r][0] += vv[r] * h.x; o[r][1] += vv[r] * h.y;
            o[r][2] += vv[r] * h.z; o[r][3] += vv[r] * h.w;
        }
    }

    float* os = g_outp8[j] + ((size_t)b * Nn + i * 128) * 64;
#pragma unroll
    for (int r = 0; r < 4; r++)
        *reinterpret_cast<float4*>(&os[(size_t)(rq * 4 + r) * 64 + cq * 4]) =
            make_float4(o[r][0], o[r][1], o[r][2], o[r][3]);
}

// ---------------------------------------------------------------------------
__global__ void out_reduce(const float* __restrict__ bias, float* __restrict__ out) {
    int idx = blockIdx.x * 256 + threadIdx.x;
    if (idx < Bb * Nn * Dd) {
        float s = bias[idx & 63];
#pragma unroll
        for (int q = 0; q < NT8; q++) s += g_outp8[q][idx];
        out[idx] = s;
    }
}

// ---------------------------------------------------------------------------
extern "C" void kernel_launch(void* const* d_in, const int* in_sizes, int n_in,
                              void* d_out, int out_size) {
    const float* H_v   = (const float*)d_in[0];
    const float* H_e   = (const float*)d_in[1];
    // d_in[2] = adj_e : unused by the reference math
    const float* adj_v = (const float*)d_in[3];
    const float* T     = (const float*)d_in[4];
    const float* W     = (const float*)d_in[5];
    const float* p     = (const float*)d_in[6];
    const float* bias  = (const float*)d_in[7];
    float* out = (float*)d_out;

    static bool attr_set = false;
    if (!attr_set) {
        cudaFuncSetAttribute(mult_partial, cudaFuncAttributeMaxDynamicSharedMemorySize,
                             MULT_SMEM);
        cudaFuncSetAttribute(combine_out, cudaFuncAttributeMaxDynamicSharedMemorySize,
                             CO_SMEM);
        attr_set = true;
    }

    scale_kernel<<<(Bb * Ee + 255) / 256, 256>>>(H_e, p);
    hw_kernel<<<(Bb * Nn) / 4, dim3(64, 4)>>>(H_v, W);
    mult_partial<<<Bb * PAIRS8 * KSPLIT, 256, MULT_SMEM>>>(T);
    combine_out<<<Bb * NT8 * NT8, 512, CO_SMEM>>>(adj_v);
    out_reduce<<<(Bb * Nn * Dd + 255) / 256, 256>>>(bias, out);

    // Second tuple output: H_e pass-through, appended after `output`
    const long long out_elems = (long long)Bb * Nn * Dd;     // 131072
    const long long he_elems  = (long long)Bb * Ee * 64;     // 1048576
    if ((long long)out_size >= out_elems + he_elems) {
        cudaMemcpyAsync(out + out_elems, H_e,
                        (size_t)he_elems * sizeof(float),
                        cudaMemcpyDeviceToDevice, 0);
    }
}

// round 14
// speedup vs baseline: 1.3323x; 1.0432x over previous
#include <cuda_runtime.h>
#include <cuda_bf16.h>
#include <cstdint>

// Problem constants
#define Bb 2
#define Nn 1024
#define Ee 8192
#define Dd 64
#define NT8 8            // 8 tiles of 128 along N
#define PAIRS8 36        // upper-triangular tile pairs
#define KC 32            // K elements per stage
#define KSPLIT 4
#define KQ (Ee / KSPLIT)           // 2048
#define NCHUNK (KQ / KC)           // 64

// ---------------------------------------------------------------------------
// Device scratch
// ---------------------------------------------------------------------------
__device__ float g_scale[Bb * Ee];
__device__ float g_hw[Bb * Nn * Dd];
__device__ float g_part[(size_t)Bb * PAIRS8 * KSPLIT * 128 * 128];
__device__ float g_outp16[16][Bb * Nn * Dd];

// ---------------------------------------------------------------------------
// Portable PTX helpers
// ---------------------------------------------------------------------------
__device__ __forceinline__ uint32_t smem_u32(const void* p) {
    uint32_t a;
    asm("{ .reg .u64 t; cvta.to.shared.u64 t, %1; cvt.u32.u64 %0, t; }" : "=r"(a) : "l"(p));
    return a;
}
#define CP16(dst, src) \
    asm volatile("cp.async.cg.shared.global [%0], [%1], 16;" :: "r"(dst), "l"(src))
#define CP_COMMIT() asm volatile("cp.async.commit_group;")
#define CP_WAIT0()  asm volatile("cp.async.wait_group 0;")
#define CP_WAIT1()  asm volatile("cp.async.wait_group 1;")

__device__ __forceinline__ void ldsm4(uint32_t* r, uint32_t addr) {
    asm volatile("ldmatrix.sync.aligned.m8n8.x4.shared.b16 {%0,%1,%2,%3}, [%4];"
                 : "=r"(r[0]), "=r"(r[1]), "=r"(r[2]), "=r"(r[3]) : "r"(addr));
}
__device__ __forceinline__ void mma_tf32(float* c, const uint32_t* a, const uint32_t* b) {
    asm volatile(
        "mma.sync.aligned.m16n8k8.row.col.f32.tf32.tf32.f32 "
        "{%0,%1,%2,%3}, {%4,%5,%6,%7}, {%8,%9}, {%0,%1,%2,%3};"
        : "+f"(c[0]), "+f"(c[1]), "+f"(c[2]), "+f"(c[3])
        : "r"(a[0]), "r"(a[1]), "r"(a[2]), "r"(a[3]), "r"(b[0]), "r"(b[1]));
}

// ---------------------------------------------------------------------------
// pre_kernel: fused scale (blocks 0..63) + HW = H_v@W (blocks 64..575)
// ---------------------------------------------------------------------------
__global__ void pre_kernel(const float* __restrict__ H_e,
                           const float* __restrict__ p,
                           const float* __restrict__ H_v,
                           const float* __restrict__ W) {
    __shared__ float sm[64 * 64 + 4 * 64];
    int bid = blockIdx.x, tid = threadIdx.x;
    if (bid < 64) {
        if (tid < 64) sm[tid] = p[tid];
        __syncthreads();
        int r = bid * 256 + tid;
        const float4* he = reinterpret_cast<const float4*>(H_e + (size_t)r * 64);
        float s = 0.f;
#pragma unroll
        for (int i = 0; i < 16; i++) {
            float4 v = he[i];
            s += v.x * sm[i * 4 + 0] + v.y * sm[i * 4 + 1] +
                 v.z * sm[i * 4 + 2] + v.w * sm[i * 4 + 3];
        }
        g_scale[r] = s;
    } else {
        float* ws = sm;
        float* hv = sm + 64 * 64;
        int tx = tid & 63, ty = tid >> 6;
        for (int i = tid; i < 64 * 64; i += 256) ws[i] = W[i];
        int row0 = (bid - 64) * 4;
        hv[ty * 64 + tx] = H_v[(size_t)(row0 + ty) * 64 + tx];
        __syncthreads();
        float acc = 0.f;
#pragma unroll
        for (int k = 0; k < 64; k++) acc += hv[ty * 64 + k] * ws[k * 64 + tx];
        g_hw[(size_t)(row0 + ty) * 64 + tx] = acc;
    }
}

// ---------------------------------------------------------------------------
// mult partial (R13-proven): 128x128 tile, quarter-K per CTA, tf32 m16n8k8.
// Raw f32 T for both tiles; per-k scale applied to A fragments in registers.
// ---------------------------------------------------------------------------
#define STRIDE_W 36
#define STAGE_WORDS (128 * STRIDE_W)           // per array: 4608 words
#define OFF_B_BYTES (STAGE_WORDS * 4)          // 18432
#define OFF_S_BYTES (2 * STAGE_WORDS * 4)      // 36864 (32-float s block)
#define STAGE_BYTES (OFF_S_BYTES + 128)        // 36992
#define MULT_SMEM (3 * STAGE_BYTES)            // 110976
#define ROWB (STRIDE_W * 4)                    // 144 bytes per row
#define MTSTEP (16 * ROWB)                     // 2304 bytes per 16-row block

__global__ void __launch_bounds__(256, 2)
mult_partial(const float* __restrict__ T) {
    extern __shared__ __align__(16) char smraw[];
    uint32_t stg = smem_u32(smraw);

    int tid = threadIdx.x;
    int wid = tid >> 5;
    int lid = tid & 31;
    int wm = wid & 1;
    int wn = wid >> 1;

    int p2 = blockIdx.x;
    int pair = p2 >> 2;
    int ksp = p2 & 3;
    int b = pair / PAIRS8;
    int t = pair % PAIRS8;
    int ti = 0, rem = t;
    while (rem >= NT8 - ti) { rem -= NT8 - ti; ti++; }
    int tj = ti + rem;

    size_t rowA = (size_t)(b * Nn + ti * 128);
    size_t rowB = (size_t)(b * Nn + tj * 128);
    int kbase = ksp * KQ;
    const float* scg = g_scale + b * Ee;

    auto load_stage = [&](int sidx, int k0) {
        uint32_t sb = stg + sidx * STAGE_BYTES;
#pragma unroll
        for (int i = 0; i < 4; i++) {
            int chunk = tid + i * 256;
            int row = chunk >> 3, cc = chunk & 7;
            uint32_t d = (uint32_t)(row * ROWB + cc * 16);
            CP16(sb + d, T + (rowA + row) * (size_t)Ee + k0 + cc * 4);
            CP16(sb + OFF_B_BYTES + d, T + (rowB + row) * (size_t)Ee + k0 + cc * 4);
        }
        if (tid < 8)
            CP16(sb + OFF_S_BYTES + tid * 16, scg + k0 + tid * 4);
        CP_COMMIT();
    };

    float acc[4][4][4];
#pragma unroll
    for (int i = 0; i < 4; i++)
#pragma unroll
        for (int j = 0; j < 4; j++)
#pragma unroll
            for (int q = 0; q < 4; q++) acc[i][j][q] = 0.f;

    load_stage(0, kbase);
    load_stage(1, kbase + KC);

    uint32_t a_lane = (uint32_t)(((lid & 7) + ((lid >> 3) & 1) * 8) * ROWB +
                                 (lid >> 4) * 16);
    uint32_t b_lane = (uint32_t)((((lid >> 4) * 8) + (lid & 7)) * ROWB +
                                 (((lid >> 3) & 1) * 16));
    uint32_t a_base0 = (uint32_t)(wm * 64 * ROWB) + a_lane;
    uint32_t b_base0 = (uint32_t)OFF_B_BYTES + (uint32_t)(wn * 32 * ROWB) + b_lane;
    int skc = lid & 3;

    for (int s = 0; s < NCHUNK; s++) {
        if (s < NCHUNK - 1) CP_WAIT1(); else CP_WAIT0();
        __syncthreads();
        uint32_t sb = stg + (s % 3) * STAGE_BYTES;
        uint32_t ab = sb + a_base0;
        uint32_t bb = sb + b_base0;
        const float* sS = reinterpret_cast<const float*>(
            smraw + (size_t)(sb - stg) + OFF_S_BYTES);

#pragma unroll
        for (int ks = 0; ks < 4; ks++) {
            float sv0 = sS[ks * 8 + skc];
            float sv1 = sS[ks * 8 + 4 + skc];
            uint32_t af[4][4], bq[2][4];
#pragma unroll
            for (int mt = 0; mt < 4; mt++)
                ldsm4(af[mt], ab + mt * MTSTEP + ks * 32);
#pragma unroll
            for (int ntp = 0; ntp < 2; ntp++)
                ldsm4(bq[ntp], bb + ntp * MTSTEP + ks * 32);
#pragma unroll
            for (int mt = 0; mt < 4; mt++) {
                af[mt][0] = __float_as_uint(__uint_as_float(af[mt][0]) * sv0);
                af[mt][1] = __float_as_uint(__uint_as_float(af[mt][1]) * sv0);
                af[mt][2] = __float_as_uint(__uint_as_float(af[mt][2]) * sv1);
                af[mt][3] = __float_as_uint(__uint_as_float(af[mt][3]) * sv1);
            }
#pragma unroll
            for (int mt = 0; mt < 4; mt++)
#pragma unroll
                for (int nt = 0; nt < 4; nt++)
                    mma_tf32(acc[mt][nt], af[mt], &bq[nt >> 1][(nt & 1) * 2]);
        }
        if (s + 2 < NCHUNK) load_stage((s + 2) % 3, kbase + (s + 2) * KC);
    }

    float* pt = g_part + (size_t)p2 * 128 * 128;
#pragma unroll
    for (int mt = 0; mt < 4; mt++)
#pragma unroll
        for (int nt = 0; nt < 4; nt++) {
            int r = wm * 64 + mt * 16 + (lid >> 2);
            int c = wn * 32 + nt * 8 + (lid & 3) * 2;
            *reinterpret_cast<float2*>(pt + (size_t)r * 128 + c) =
                make_float2(acc[mt][nt][0], acc[mt][nt][1]);
            *reinterpret_cast<float2*>(pt + (size_t)(r + 8) * 128 + c) =
                make_float2(acc[mt][nt][2], acc[mt][nt][3]);
        }
}

// ---------------------------------------------------------------------------
// combine_out: per (b, i, j, kh): for k-half kh of tile (i,j),
// v = mask(sum of 4 partials) * adj_v; out16[slot j*2+kh][rows i*128..]
//   = v_half @ HW[j-block k-half]. grid = Bb*64*2 = 256, 512 threads.
// smem: vs[64][132] + HWs[64][68] = 51200 B -> 2 CTAs/SM.
// ---------------------------------------------------------------------------
#define CO_SMEM (64 * 132 * 4 + 64 * 68 * 4)

__global__ void __launch_bounds__(512, 2)
combine_out(const float* __restrict__ adj_v) {
    extern __shared__ float cs[];
    float* vs = cs;                      // [k][r] stride 132 (k local 0..63)
    float* HWs = cs + 64 * 132;          // [k][d] stride 68

    int tid = threadIdx.x;
    int bid = blockIdx.x;
    int b = bid >> 7;
    int r2 = bid & 127;
    int ij = r2 >> 1, kh = r2 & 1;
    int i = ij >> 3, j = ij & 7;

    // HW rows j*128 + kh*64 .. +64
    const float* HWb = g_hw + (size_t)b * Nn * Dd + (size_t)(j * 128 + kh * 64) * 64;
    for (int idx = tid; idx < 4096; idx += 512)
        HWs[(idx >> 6) * 68 + (idx & 63)] = HWb[idx];

    int lo = i < j ? i : j, hi = i < j ? j : i;
    int p = 8 * lo - lo * (lo - 1) / 2 + (hi - lo);
    const float* p0 = g_part + ((size_t)(b * PAIRS8 + p) * 4 + 0) * 16384;
    const float* p1 = g_part + ((size_t)(b * PAIRS8 + p) * 4 + 1) * 16384;
    const float* p2 = g_part + ((size_t)(b * PAIRS8 + p) * 4 + 2) * 16384;
    const float* p3 = g_part + ((size_t)(b * PAIRS8 + p) * 4 + 3) * 16384;

    if (i <= j) {
        // vs[c][r] = m[r][kh*64+c] : read columns kh*64.. of stored rows
        for (int idx = tid; idx < 8192; idx += 512) {
            int r = idx >> 6, c = idx & 63;
            int src = r * 128 + kh * 64 + c;
            vs[c * 132 + r] = (p0[src] + p1[src]) + (p2[src] + p3[src]);
        }
    } else {
        // vs[k][r] = stored_ji[kh*64+k][r] (= m_ij[r][kh*64+k])
        for (int idx = tid; idx < 8192; idx += 512) {
            int rp = idx >> 7, cp = idx & 127;
            int src = (kh * 64 + rp) * 128 + cp;
            vs[rp * 132 + cp] = (p0[src] + p1[src]) + (p2[src] + p3[src]);
        }
    }
    __syncthreads();

    // mask + adj multiply: element (r, kh*64+c) of tile (i,j)
    const float* av = adj_v + (size_t)b * Nn * Nn;
    for (int idx = tid; idx < 8192; idx += 512) {
        int r = idx >> 6, c = idx & 63;
        int n = i * 128 + r, mcol = j * 128 + kh * 64 + c;
        float m = vs[c * 132 + r];
        if (i == j && r == kh * 64 + c) m = 1.f;
        vs[c * 132 + r] = m * av[(size_t)n * Nn + mcol];
    }
    __syncthreads();

    int rq = tid & 31;          // rows rq*4 .. +3
    int cq = tid >> 5;          // cols cq*4 .. +3
    float o[4][4];
#pragma unroll
    for (int r = 0; r < 4; r++)
#pragma unroll
        for (int c = 0; c < 4; c++) o[r][c] = 0.f;

    for (int k = 0; k < 64; k++) {
        float4 h = *reinterpret_cast<float4*>(&HWs[k * 68 + cq * 4]);
        float4 v = *reinterpret_cast<float4*>(&vs[k * 132 + rq * 4]);
        float vv[4] = {v.x, v.y, v.z, v.w};
#pragma unroll
        for (int r = 0; r < 4; r++) {
            o[r][0] += vv[r] * h.x; o[r][1] += vv[r] * h.y;
            o[r][2] += vv[r] * h.z; o[r][3] += vv[r] * h.w;
        }
    }

    float* os = g_outp16[j * 2 + kh] + ((size_t)b * Nn + i * 128) * 64;
#pragma unroll
    for (int r = 0; r < 4; r++)
        *reinterpret_cast<float4*>(&os[(size_t)(rq * 4 + r) * 64 + cq * 4]) =
            make_float4(o[r][0], o[r][1], o[r][2], o[r][3]);
}

// ---------------------------------------------------------------------------
// out_reduce: sum 16 slots + bias, and copy the H_e pass-through output.
// ---------------------------------------------------------------------------
#define OUT_ELEMS (Bb * Nn * Dd)               // 131072
#define HE_ELEMS (Bb * Ee * 64)                // 1048576

__global__ void out_reduce(const float* __restrict__ bias,
                           const float* __restrict__ H_e,
                           float* __restrict__ out, int do_he) {
    int idx = blockIdx.x * 256 + threadIdx.x;
    if (idx < OUT_ELEMS) {
        float s = bias[idx & 63];
#pragma unroll
        for (int q = 0; q < 16; q++) s += g_outp16[q][idx];
        out[idx] = s;
    } else if (do_he) {
        int jdx = idx - OUT_ELEMS;
        if (jdx < HE_ELEMS) out[OUT_ELEMS + jdx] = H_e[jdx];
    }
}

// ---------------------------------------------------------------------------
extern "C" void kernel_launch(void* const* d_in, const int* in_sizes, int n_in,
                              void* d_out, int out_size) {
    const float* H_v   = (const float*)d_in[0];
    const float* H_e   = (const float*)d_in[1];
    // d_in[2] = adj_e : unused by the reference math
    const float* adj_v = (const float*)d_in[3];
    const float* T     = (const float*)d_in[4];
    const float* W     = (const float*)d_in[5];
    const float* p     = (const float*)d_in[6];
    const float* bias  = (const float*)d_in[7];
    float* out = (float*)d_out;

    static bool attr_set = false;
    if (!attr_set) {
        cudaFuncSetAttribute(mult_partial, cudaFuncAttributeMaxDynamicSharedMemorySize,
                             MULT_SMEM);
        cudaFuncSetAttribute(combine_out, cudaFuncAttributeMaxDynamicSharedMemorySize,
                             CO_SMEM);
        attr_set = true;
    }

    pre_kernel<<<576, 256>>>(H_e, p, H_v, W);
    mult_partial<<<Bb * PAIRS8 * KSPLIT, 256, MULT_SMEM>>>(T);
    combine_out<<<Bb * 64 * 2, 512, CO_SMEM>>>(adj_v);

    int do_he = ((long long)out_size >= (long long)OUT_ELEMS + HE_ELEMS) ? 1 : 0;
    int total = do_he ? (OUT_ELEMS + HE_ELEMS) : OUT_ELEMS;
    out_reduce<<<(total + 255) / 256, 256>>>(bias, H_e, out, do_he);
}